// round 4
// baseline (speedup 1.0000x reference)
#include <cuda_runtime.h>
#include <math.h>

#define NN   50000
#define NE   800000
#define ET   850000   // NE + NN self loops
#define IND  256
#define HID  128
#define NG   64
#define NEG_SLOPE 0.2f
#define SCAN_B ((NN + 255) / 256)   // 196

// ---------------- scratch (no allocations allowed) ----------------
__device__ float g_bufA[NN * HID];   // 25.6 MB
__device__ float g_bufB[NN * HID];   // 25.6 MB
__device__ float g_as[NN];
__device__ float g_ad[NN];
__device__ float g_w[ET];
__device__ int   g_batch[NN];
__device__ int   g_counts[NN];
__device__ int   g_roff[NN + 1];
__device__ int   g_cursor[NN];
__device__ int   g_csr[ET];          // src node id per CSR slot (grouped by dst)
__device__ int   g_bsum[SCAN_B];
__device__ int   g_boff[SCAN_B];
__device__ float g_pool[NG * HID];
__device__ int   g_gcnt[NG];
__device__ int   g_flag[2];

// ---------------- dtype sniffing (int64 vs int32) ----------------
__global__ void detect_kernel(const unsigned* __restrict__ e,
                              const unsigned* __restrict__ b) {
    if (threadIdx.x == 0 && blockIdx.x == 0) {
        int nz = 0;
        for (int i = 0; i < 1024; i++) nz += (e[2 * i + 1] != 0u);
        g_flag[0] = (nz == 0);
        nz = 0;
        for (int i = 0; i < 256; i++) nz += (b[NN - 1 - 2 * i] != 0u);
        g_flag[1] = (nz == 0);
    }
}

// ---------------- zero small scratch (counts=1 encodes self loop) ----------------
__global__ void zero_kernel() {
    int stride = gridDim.x * blockDim.x;
    int i0 = blockIdx.x * blockDim.x + threadIdx.x;
    for (int j = i0; j < NN; j += stride) g_counts[j] = 1;
    for (int j = i0; j < NG * HID; j += stride) g_pool[j] = 0.f;
    for (int j = i0; j < NG; j += stride) g_gcnt[j] = 0;
}

// ---------------- histogram over dst + batch decode ----------------
__global__ void hist_kernel(const void* __restrict__ edge,
                            const void* __restrict__ batch) {
    int e64 = g_flag[0], b64 = g_flag[1];
    int i = blockIdx.x * blockDim.x + threadIdx.x;
    if (i < NE) {
        int d = e64 ? (int)((const long long*)edge)[NE + i]
                    : ((const int*)edge)[NE + i];
        atomicAdd(&g_counts[d], 1);
    }
    if (i < NN) {
        int b = b64 ? (int)((const long long*)batch)[i]
                    : ((const int*)batch)[i];
        g_batch[i] = b;
        atomicAdd(&g_gcnt[b], 1);
    }
}

// ---------------- parallel exclusive scan (3 kernels) ----------------
__global__ void scanA_kernel() {
    __shared__ int ws[8];
    int i = blockIdx.x * 256 + threadIdx.x;
    int lane = threadIdx.x & 31, wrp = threadIdx.x >> 5;
    int v = (i < NN) ? g_counts[i] : 0;
    int incl = v;
#pragma unroll
    for (int o = 1; o < 32; o <<= 1) {
        int t = __shfl_up_sync(0xffffffffu, incl, o);
        if (lane >= o) incl += t;
    }
    if (lane == 31) ws[wrp] = incl;
    __syncthreads();
    if (threadIdx.x < 8) {
        int s = ws[threadIdx.x];
        int inc2 = s;
#pragma unroll
        for (int o = 1; o < 8; o <<= 1) {
            int t = __shfl_up_sync(0xffu, inc2, o);
            if (threadIdx.x >= (unsigned)o) inc2 += t;
        }
        ws[threadIdx.x] = inc2 - s;
        if (threadIdx.x == 7) g_bsum[blockIdx.x] = inc2;
    }
    __syncthreads();
    if (i < NN) g_roff[i] = ws[wrp] + incl - v;
}

__global__ void scanB_kernel() {
    __shared__ int ws[8];
    int t = threadIdx.x;
    int lane = t & 31, wrp = t >> 5;
    int v = (t < SCAN_B) ? g_bsum[t] : 0;
    int incl = v;
#pragma unroll
    for (int o = 1; o < 32; o <<= 1) {
        int x = __shfl_up_sync(0xffffffffu, incl, o);
        if (lane >= o) incl += x;
    }
    if (lane == 31) ws[wrp] = incl;
    __syncthreads();
    if (t < 8) {
        int s = ws[t];
        int inc2 = s;
#pragma unroll
        for (int o = 1; o < 8; o <<= 1) {
            int x = __shfl_up_sync(0xffu, inc2, o);
            if (t >= o) inc2 += x;
        }
        ws[t] = inc2 - s;
    }
    __syncthreads();
    if (t < SCAN_B) g_boff[t] = ws[wrp] + incl - v;
}

__global__ void scanC_kernel() {
    int i = blockIdx.x * 256 + threadIdx.x;
    if (i == 0) g_roff[NN] = ET;
    if (i >= NN) return;
    int r = g_roff[i] + g_boff[i >> 8];
    g_roff[i] = r;
    g_cursor[i] = r;
}

// ---------------- CSR fill (decodes edge input directly) ----------------
__global__ void fill_kernel(const void* __restrict__ edge) {
    int e64 = g_flag[0];
    int i = blockIdx.x * blockDim.x + threadIdx.x;
    if (i >= ET) return;
    int s, d;
    if (i < NE) {
        if (e64) {
            s = (int)((const long long*)edge)[i];
            d = (int)((const long long*)edge)[NE + i];
        } else {
            s = ((const int*)edge)[i];
            d = ((const int*)edge)[NE + i];
        }
    } else {
        s = d = i - NE;
    }
    int p = atomicAdd(&g_cursor[d], 1);
    g_csr[p] = s;
}

// ---------------- SGEMM + fused alpha epilogue ----------------
template <int K>
__global__ void __launch_bounds__(256)
gemm_kernel(const float* __restrict__ A, const float* __restrict__ B,
            float* __restrict__ C, int M,
            const float* __restrict__ asrc, const float* __restrict__ adst) {
    const int BM = 64, BN = 128, BK = 16;
    __shared__ float As[BK][BM];
    __shared__ float Bs[BK][BN];
    int tid = threadIdx.x;
    int m0 = blockIdx.x * BM;
    int ty = tid >> 5;
    int tx = tid & 31;

    float acc[8][4];
#pragma unroll
    for (int i = 0; i < 8; i++)
#pragma unroll
        for (int j = 0; j < 4; j++) acc[i][j] = 0.f;

    int arow = tid >> 2;
    int ak4  = (tid & 3) * 4;
    int bn4  = (tid & 31) * 4;
    int bk   = tid >> 5;

    for (int k0 = 0; k0 < K; k0 += BK) {
        float4 av = make_float4(0.f, 0.f, 0.f, 0.f);
        int gm = m0 + arow;
        if (gm < M) av = *(const float4*)(A + (size_t)gm * K + k0 + ak4);
        As[ak4 + 0][arow] = av.x; As[ak4 + 1][arow] = av.y;
        As[ak4 + 2][arow] = av.z; As[ak4 + 3][arow] = av.w;

        float4 bv0 = *(const float4*)(B + (size_t)(k0 + bk) * BN + bn4);
        float4 bv1 = *(const float4*)(B + (size_t)(k0 + bk + 8) * BN + bn4);
        *(float4*)&Bs[bk][bn4]     = bv0;
        *(float4*)&Bs[bk + 8][bn4] = bv1;
        __syncthreads();

#pragma unroll
        for (int k = 0; k < BK; k++) {
            float4 b4 = *(const float4*)&Bs[k][tx * 4];
            float4 a0 = *(const float4*)&As[k][ty * 8];
            float4 a1 = *(const float4*)&As[k][ty * 8 + 4];
            float a[8] = {a0.x, a0.y, a0.z, a0.w, a1.x, a1.y, a1.z, a1.w};
#pragma unroll
            for (int i = 0; i < 8; i++) {
                acc[i][0] += a[i] * b4.x;
                acc[i][1] += a[i] * b4.y;
                acc[i][2] += a[i] * b4.z;
                acc[i][3] += a[i] * b4.w;
            }
        }
        __syncthreads();
    }

    float4 asv = ((const float4*)asrc)[tx];
    float4 adv = ((const float4*)adst)[tx];
#pragma unroll
    for (int i = 0; i < 8; i++) {
        int gm = m0 + ty * 8 + i;
        float s = acc[i][0] * asv.x + acc[i][1] * asv.y +
                  acc[i][2] * asv.z + acc[i][3] * asv.w;
        float d = acc[i][0] * adv.x + acc[i][1] * adv.y +
                  acc[i][2] * adv.z + acc[i][3] * adv.w;
#pragma unroll
        for (int o = 16; o; o >>= 1) {
            s += __shfl_xor_sync(0xffffffffu, s, o);
            d += __shfl_xor_sync(0xffffffffu, d, o);
        }
        if (gm < M) {
            *(float4*)(C + (size_t)gm * BN + tx * 4) =
                make_float4(acc[i][0], acc[i][1], acc[i][2], acc[i][3]);
            if (tx == 0) { g_as[gm] = s; g_ad[gm] = d; }
        }
    }
}

// ---------------- fused attention softmax + aggregate (+bias/relu/pool) ----------------
// warp per destination node; no max-pass (exp safe in fp32 here).
// Pass B: stage csr/w coalesced per warp, broadcast via shfl, 4 gathers in flight.
template <int POOL>
__global__ void __launch_bounds__(256)
attn_kernel(const float* __restrict__ h, const float* __restrict__ bias,
            float* __restrict__ out) {
    int d = blockIdx.x * 8 + (threadIdx.x >> 5);
    if (d >= NN) return;
    int lane = threadIdx.x & 31;
    int beg = g_roff[d], end = g_roff[d + 1];
    float add = g_ad[d];

    // pass A: w = exp(leakyrelu(e)), cache in g_w, accumulate denominator
    float den = 0.f;
    for (int i = beg + lane; i < end; i += 32) {
        float e = __ldg(&g_as[g_csr[i]]) + add;
        e = e > 0.f ? e : NEG_SLOPE * e;
        float w = __expf(e);
        g_w[i] = w;
        den += w;
    }
#pragma unroll
    for (int o = 16; o; o >>= 1) den += __shfl_xor_sync(0xffffffffu, den, o);
    float inv = 1.f / den;
    __syncwarp();

    // pass B: weighted aggregation
    float4 acc = make_float4(0.f, 0.f, 0.f, 0.f);
    for (int base = beg; base < end; base += 32) {
        int idx = base + lane;
        bool val = idx < end;
        int   sv = val ? g_csr[idx] : 0;
        float cv = val ? g_w[idx] * inv : 0.f;
        int cnt = min(32, end - base);
        for (int j = 0; j < cnt; j += 4) {
            int   s0 = __shfl_sync(0xffffffffu, sv, j);
            int   s1 = __shfl_sync(0xffffffffu, sv, j + 1);
            int   s2 = __shfl_sync(0xffffffffu, sv, j + 2);
            int   s3 = __shfl_sync(0xffffffffu, sv, j + 3);
            float c0 = __shfl_sync(0xffffffffu, cv, j);
            float c1 = __shfl_sync(0xffffffffu, cv, j + 1);
            float c2 = __shfl_sync(0xffffffffu, cv, j + 2);
            float c3 = __shfl_sync(0xffffffffu, cv, j + 3);
            float4 h0 = __ldg(&((const float4*)(h + (size_t)s0 * HID))[lane]);
            float4 h1 = __ldg(&((const float4*)(h + (size_t)s1 * HID))[lane]);
            float4 h2 = __ldg(&((const float4*)(h + (size_t)s2 * HID))[lane]);
            float4 h3 = __ldg(&((const float4*)(h + (size_t)s3 * HID))[lane]);
            acc.x += c0 * h0.x + c1 * h1.x + c2 * h2.x + c3 * h3.x;
            acc.y += c0 * h0.y + c1 * h1.y + c2 * h2.y + c3 * h3.y;
            acc.z += c0 * h0.z + c1 * h1.z + c2 * h2.z + c3 * h3.z;
            acc.w += c0 * h0.w + c1 * h1.w + c2 * h2.w + c3 * h3.w;
        }
    }

    float4 bb = ((const float4*)bias)[lane];
    acc.x = fmaxf(acc.x + bb.x, 0.f);
    acc.y = fmaxf(acc.y + bb.y, 0.f);
    acc.z = fmaxf(acc.z + bb.z, 0.f);
    acc.w = fmaxf(acc.w + bb.w, 0.f);

    if (POOL) {
        int g = g_batch[d];
        float* p = g_pool + g * HID + lane * 4;
        atomicAdd(p + 0, acc.x);
        atomicAdd(p + 1, acc.y);
        atomicAdd(p + 2, acc.z);
        atomicAdd(p + 3, acc.w);
    } else {
        ((float4*)(out + (size_t)d * HID))[lane] = acc;
    }
}

// ---------------- classifier head ----------------
__global__ void head_kernel(const float* __restrict__ Wc,
                            const float* __restrict__ bc,
                            float* __restrict__ out) {
    int g = blockIdx.x;
    int lane = threadIdx.x;
    float s = 0.f;
#pragma unroll
    for (int j = lane; j < HID; j += 32) s += g_pool[g * HID + j] * Wc[j];
#pragma unroll
    for (int o = 16; o; o >>= 1) s += __shfl_xor_sync(0xffffffffu, s, o);
    if (lane == 0) {
        float c = fmaxf((float)g_gcnt[g], 1.f);
        float v = s / c + bc[0];
        out[g] = 1.f / (1.f + expf(-v));
    }
}

// ---------------- launch ----------------
extern "C" void kernel_launch(void* const* d_in, const int* in_sizes, int n_in,
                              void* d_out, int out_size) {
    const float* x    = (const float*)d_in[0];
    const void*  edge = d_in[1];
    const void*  batch= d_in[2];
    const float* W1   = (const float*)d_in[3];
    const float* as1  = (const float*)d_in[4];
    const float* ad1  = (const float*)d_in[5];
    const float* b1   = (const float*)d_in[6];
    const float* W2   = (const float*)d_in[7];
    const float* as2  = (const float*)d_in[8];
    const float* ad2  = (const float*)d_in[9];
    const float* b2   = (const float*)d_in[10];
    const float* Wc   = (const float*)d_in[11];
    const float* bc   = (const float*)d_in[12];
    float* out = (float*)d_out;
    (void)in_sizes; (void)n_in; (void)out_size;

    float* bufA; cudaGetSymbolAddress((void**)&bufA, g_bufA);
    float* bufB; cudaGetSymbolAddress((void**)&bufB, g_bufB);

    const int EB = (ET + 255) / 256;
    const int HB = (NE + 255) / 256;
    const int WB = (NN + 7) / 8;

    detect_kernel<<<1, 32>>>((const unsigned*)edge, (const unsigned*)batch);
    zero_kernel<<<64, 256>>>();
    hist_kernel<<<HB, 256>>>(edge, batch);
    scanA_kernel<<<SCAN_B, 256>>>();
    scanB_kernel<<<1, 256>>>();
    scanC_kernel<<<SCAN_B, 256>>>();
    fill_kernel<<<EB, 256>>>(edge);

    // ---- layer 1 ----
    gemm_kernel<IND><<<(NN + 63) / 64, 256>>>(x, W1, bufA, NN, as1, ad1);
    attn_kernel<0><<<WB, 256>>>(bufA, b1, bufB);

    // ---- layer 2 ----
    gemm_kernel<HID><<<(NN + 63) / 64, 256>>>(bufB, W2, bufA, NN, as2, ad2);
    attn_kernel<1><<<WB, 256>>>(bufA, b2, nullptr);

    head_kernel<<<NG, 32>>>(Wc, bc, out);
}

// round 5
// speedup vs baseline: 1.0802x; 1.0802x over previous
#include <cuda_runtime.h>
#include <math.h>

#define NN   50000
#define NE   800000
#define ET   850000   // NE + NN self loops
#define IND  256
#define HID  128
#define NG   64
#define NEG_SLOPE 0.2f
#define SCAN_B ((NN + 255) / 256)   // 196

// ---------------- scratch (no allocations allowed) ----------------
__device__ float g_bufA[NN * HID];   // 25.6 MB
__device__ float g_bufB[NN * HID];   // 25.6 MB
__device__ float g_as[NN];
__device__ float g_ad[NN];
__device__ float g_w[ET];
__device__ int   g_batch[NN];
__device__ int   g_counts[NN];
__device__ int   g_roff[NN + 1];
__device__ int   g_cursor[NN];
__device__ int   g_csr[ET];          // src node id per CSR slot (grouped by dst)
__device__ int   g_bsum[SCAN_B];
__device__ int   g_boff[SCAN_B];
__device__ float g_pool[NG * HID];
__device__ int   g_gcnt[NG];
__device__ int   g_flag[2];

// ---------------- dtype sniffing (int64 vs int32) ----------------
__global__ void detect_kernel(const unsigned* __restrict__ e,
                              const unsigned* __restrict__ b) {
    if (threadIdx.x == 0 && blockIdx.x == 0) {
        int nz = 0;
        for (int i = 0; i < 1024; i++) nz += (e[2 * i + 1] != 0u);
        g_flag[0] = (nz == 0);
        nz = 0;
        for (int i = 0; i < 256; i++) nz += (b[NN - 1 - 2 * i] != 0u);
        g_flag[1] = (nz == 0);
    }
}

// ---------------- zero small scratch (counts=1 encodes self loop) ----------------
__global__ void zero_kernel() {
    int stride = gridDim.x * blockDim.x;
    int i0 = blockIdx.x * blockDim.x + threadIdx.x;
    for (int j = i0; j < NN; j += stride) g_counts[j] = 1;
    for (int j = i0; j < NG * HID; j += stride) g_pool[j] = 0.f;
    for (int j = i0; j < NG; j += stride) g_gcnt[j] = 0;
}

// ---------------- histogram over dst + batch decode ----------------
__global__ void hist_kernel(const void* __restrict__ edge,
                            const void* __restrict__ batch) {
    int e64 = g_flag[0], b64 = g_flag[1];
    int i = blockIdx.x * blockDim.x + threadIdx.x;
    if (i < NE) {
        int d = e64 ? (int)((const long long*)edge)[NE + i]
                    : ((const int*)edge)[NE + i];
        atomicAdd(&g_counts[d], 1);
    }
    if (i < NN) {
        int b = b64 ? (int)((const long long*)batch)[i]
                    : ((const int*)batch)[i];
        g_batch[i] = b;
        atomicAdd(&g_gcnt[b], 1);
    }
}

// ---------------- parallel exclusive scan (3 kernels) ----------------
__global__ void scanA_kernel() {
    __shared__ int ws[8];
    int i = blockIdx.x * 256 + threadIdx.x;
    int lane = threadIdx.x & 31, wrp = threadIdx.x >> 5;
    int v = (i < NN) ? g_counts[i] : 0;
    int incl = v;
#pragma unroll
    for (int o = 1; o < 32; o <<= 1) {
        int t = __shfl_up_sync(0xffffffffu, incl, o);
        if (lane >= o) incl += t;
    }
    if (lane == 31) ws[wrp] = incl;
    __syncthreads();
    if (threadIdx.x < 8) {
        int s = ws[threadIdx.x];
        int inc2 = s;
#pragma unroll
        for (int o = 1; o < 8; o <<= 1) {
            int t = __shfl_up_sync(0xffu, inc2, o);
            if (threadIdx.x >= (unsigned)o) inc2 += t;
        }
        ws[threadIdx.x] = inc2 - s;
        if (threadIdx.x == 7) g_bsum[blockIdx.x] = inc2;
    }
    __syncthreads();
    if (i < NN) g_roff[i] = ws[wrp] + incl - v;
}

__global__ void scanB_kernel() {
    __shared__ int ws[8];
    int t = threadIdx.x;
    int lane = t & 31, wrp = t >> 5;
    int v = (t < SCAN_B) ? g_bsum[t] : 0;
    int incl = v;
#pragma unroll
    for (int o = 1; o < 32; o <<= 1) {
        int x = __shfl_up_sync(0xffffffffu, incl, o);
        if (lane >= o) incl += x;
    }
    if (lane == 31) ws[wrp] = incl;
    __syncthreads();
    if (t < 8) {
        int s = ws[t];
        int inc2 = s;
#pragma unroll
        for (int o = 1; o < 8; o <<= 1) {
            int x = __shfl_up_sync(0xffu, inc2, o);
            if (t >= o) inc2 += x;
        }
        ws[t] = inc2 - s;
    }
    __syncthreads();
    if (t < SCAN_B) g_boff[t] = ws[wrp] + incl - v;
}

__global__ void scanC_kernel() {
    int i = blockIdx.x * 256 + threadIdx.x;
    if (i == 0) g_roff[NN] = ET;
    if (i >= NN) return;
    int r = g_roff[i] + g_boff[i >> 8];
    g_roff[i] = r;
    g_cursor[i] = r;
}

// ---------------- CSR fill (decodes edge input directly) ----------------
__global__ void fill_kernel(const void* __restrict__ edge) {
    int e64 = g_flag[0];
    int i = blockIdx.x * blockDim.x + threadIdx.x;
    if (i >= ET) return;
    int s, d;
    if (i < NE) {
        if (e64) {
            s = (int)((const long long*)edge)[i];
            d = (int)((const long long*)edge)[NE + i];
        } else {
            s = ((const int*)edge)[i];
            d = ((const int*)edge)[NE + i];
        }
    } else {
        s = d = i - NE;
    }
    int p = atomicAdd(&g_cursor[d], 1);
    g_csr[p] = s;
}

// ---------------- SGEMM + fused alpha epilogue ----------------
template <int K>
__global__ void __launch_bounds__(256)
gemm_kernel(const float* __restrict__ A, const float* __restrict__ B,
            float* __restrict__ C, int M,
            const float* __restrict__ asrc, const float* __restrict__ adst) {
    const int BM = 64, BN = 128, BK = 16;
    __shared__ float As[BK][BM];
    __shared__ float Bs[BK][BN];
    int tid = threadIdx.x;
    int m0 = blockIdx.x * BM;
    int ty = tid >> 5;
    int tx = tid & 31;

    float acc[8][4];
#pragma unroll
    for (int i = 0; i < 8; i++)
#pragma unroll
        for (int j = 0; j < 4; j++) acc[i][j] = 0.f;

    int arow = tid >> 2;
    int ak4  = (tid & 3) * 4;
    int bn4  = (tid & 31) * 4;
    int bk   = tid >> 5;

    for (int k0 = 0; k0 < K; k0 += BK) {
        float4 av = make_float4(0.f, 0.f, 0.f, 0.f);
        int gm = m0 + arow;
        if (gm < M) av = *(const float4*)(A + (size_t)gm * K + k0 + ak4);
        As[ak4 + 0][arow] = av.x; As[ak4 + 1][arow] = av.y;
        As[ak4 + 2][arow] = av.z; As[ak4 + 3][arow] = av.w;

        float4 bv0 = *(const float4*)(B + (size_t)(k0 + bk) * BN + bn4);
        float4 bv1 = *(const float4*)(B + (size_t)(k0 + bk + 8) * BN + bn4);
        *(float4*)&Bs[bk][bn4]     = bv0;
        *(float4*)&Bs[bk + 8][bn4] = bv1;
        __syncthreads();

#pragma unroll
        for (int k = 0; k < BK; k++) {
            float4 b4 = *(const float4*)&Bs[k][tx * 4];
            float4 a0 = *(const float4*)&As[k][ty * 8];
            float4 a1 = *(const float4*)&As[k][ty * 8 + 4];
            float a[8] = {a0.x, a0.y, a0.z, a0.w, a1.x, a1.y, a1.z, a1.w};
#pragma unroll
            for (int i = 0; i < 8; i++) {
                acc[i][0] += a[i] * b4.x;
                acc[i][1] += a[i] * b4.y;
                acc[i][2] += a[i] * b4.z;
                acc[i][3] += a[i] * b4.w;
            }
        }
        __syncthreads();
    }

    float4 asv = ((const float4*)asrc)[tx];
    float4 adv = ((const float4*)adst)[tx];
#pragma unroll
    for (int i = 0; i < 8; i++) {
        int gm = m0 + ty * 8 + i;
        float s = acc[i][0] * asv.x + acc[i][1] * asv.y +
                  acc[i][2] * asv.z + acc[i][3] * asv.w;
        float d = acc[i][0] * adv.x + acc[i][1] * adv.y +
                  acc[i][2] * adv.z + acc[i][3] * adv.w;
#pragma unroll
        for (int o = 16; o; o >>= 1) {
            s += __shfl_xor_sync(0xffffffffu, s, o);
            d += __shfl_xor_sync(0xffffffffu, d, o);
        }
        if (gm < M) {
            *(float4*)(C + (size_t)gm * BN + tx * 4) =
                make_float4(acc[i][0], acc[i][1], acc[i][2], acc[i][3]);
            if (tx == 0) { g_as[gm] = s; g_ad[gm] = d; }
        }
    }
}

// ---------------- fused attention softmax + aggregate (+bias/relu/pool) ----------------
// warp per destination node; no max-pass (exp safe in fp32 here).
// Pass B: 4-way manual unroll; csr/w read via warp-uniform loads (broadcast),
// 4 independent float4 gathers issued before any FFMA -> MLP=4.
template <int POOL>
__global__ void __launch_bounds__(256)
attn_kernel(const float* __restrict__ h, const float* __restrict__ bias,
            float* __restrict__ out) {
    int d = blockIdx.x * 8 + (threadIdx.x >> 5);
    if (d >= NN) return;
    int lane = threadIdx.x & 31;
    int beg = g_roff[d], end = g_roff[d + 1];
    float add = g_ad[d];

    // pass A: w = exp(leakyrelu(e)), cache in g_w, accumulate denominator
    float den = 0.f;
    for (int i = beg + lane; i < end; i += 32) {
        float e = __ldg(&g_as[g_csr[i]]) + add;
        e = e > 0.f ? e : NEG_SLOPE * e;
        float w = __expf(e);
        g_w[i] = w;
        den += w;
    }
#pragma unroll
    for (int o = 16; o; o >>= 1) den += __shfl_xor_sync(0xffffffffu, den, o);
    float inv = 1.f / den;
    __syncwarp();

    // pass B: weighted aggregation, unroll x4
    float4 acc = make_float4(0.f, 0.f, 0.f, 0.f);
    int i = beg;
    for (; i + 4 <= end; i += 4) {
        int   s0 = g_csr[i],     s1 = g_csr[i + 1];
        int   s2 = g_csr[i + 2], s3 = g_csr[i + 3];
        float c0 = g_w[i] * inv,     c1 = g_w[i + 1] * inv;
        float c2 = g_w[i + 2] * inv, c3 = g_w[i + 3] * inv;
        float4 h0 = __ldg(&((const float4*)(h + (size_t)s0 * HID))[lane]);
        float4 h1 = __ldg(&((const float4*)(h + (size_t)s1 * HID))[lane]);
        float4 h2 = __ldg(&((const float4*)(h + (size_t)s2 * HID))[lane]);
        float4 h3 = __ldg(&((const float4*)(h + (size_t)s3 * HID))[lane]);
        acc.x += c0 * h0.x + c1 * h1.x + c2 * h2.x + c3 * h3.x;
        acc.y += c0 * h0.y + c1 * h1.y + c2 * h2.y + c3 * h3.y;
        acc.z += c0 * h0.z + c1 * h1.z + c2 * h2.z + c3 * h3.z;
        acc.w += c0 * h0.w + c1 * h1.w + c2 * h2.w + c3 * h3.w;
    }
    for (; i < end; i++) {
        int s = g_csr[i];
        float c = g_w[i] * inv;
        float4 hv = __ldg(&((const float4*)(h + (size_t)s * HID))[lane]);
        acc.x += c * hv.x; acc.y += c * hv.y;
        acc.z += c * hv.z; acc.w += c * hv.w;
    }

    float4 bb = ((const float4*)bias)[lane];
    acc.x = fmaxf(acc.x + bb.x, 0.f);
    acc.y = fmaxf(acc.y + bb.y, 0.f);
    acc.z = fmaxf(acc.z + bb.z, 0.f);
    acc.w = fmaxf(acc.w + bb.w, 0.f);

    if (POOL) {
        int g = g_batch[d];
        float* p = g_pool + g * HID + lane * 4;
        atomicAdd(p + 0, acc.x);
        atomicAdd(p + 1, acc.y);
        atomicAdd(p + 2, acc.z);
        atomicAdd(p + 3, acc.w);
    } else {
        ((float4*)(out + (size_t)d * HID))[lane] = acc;
    }
}

// ---------------- classifier head ----------------
__global__ void head_kernel(const float* __restrict__ Wc,
                            const float* __restrict__ bc,
                            float* __restrict__ out) {
    int g = blockIdx.x;
    int lane = threadIdx.x;
    float s = 0.f;
#pragma unroll
    for (int j = lane; j < HID; j += 32) s += g_pool[g * HID + j] * Wc[j];
#pragma unroll
    for (int o = 16; o; o >>= 1) s += __shfl_xor_sync(0xffffffffu, s, o);
    if (lane == 0) {
        float c = fmaxf((float)g_gcnt[g], 1.f);
        float v = s / c + bc[0];
        out[g] = 1.f / (1.f + expf(-v));
    }
}

// ---------------- launch ----------------
extern "C" void kernel_launch(void* const* d_in, const int* in_sizes, int n_in,
                              void* d_out, int out_size) {
    const float* x    = (const float*)d_in[0];
    const void*  edge = d_in[1];
    const void*  batch= d_in[2];
    const float* W1   = (const float*)d_in[3];
    const float* as1  = (const float*)d_in[4];
    const float* ad1  = (const float*)d_in[5];
    const float* b1   = (const float*)d_in[6];
    const float* W2   = (const float*)d_in[7];
    const float* as2  = (const float*)d_in[8];
    const float* ad2  = (const float*)d_in[9];
    const float* b2   = (const float*)d_in[10];
    const float* Wc   = (const float*)d_in[11];
    const float* bc   = (const float*)d_in[12];
    float* out = (float*)d_out;
    (void)in_sizes; (void)n_in; (void)out_size;

    float* bufA; cudaGetSymbolAddress((void**)&bufA, g_bufA);
    float* bufB; cudaGetSymbolAddress((void**)&bufB, g_bufB);

    const int EB = (ET + 255) / 256;
    const int HB = (NE + 255) / 256;
    const int WB = (NN + 7) / 8;

    detect_kernel<<<1, 32>>>((const unsigned*)edge, (const unsigned*)batch);
    zero_kernel<<<64, 256>>>();
    hist_kernel<<<HB, 256>>>(edge, batch);
    scanA_kernel<<<SCAN_B, 256>>>();
    scanB_kernel<<<1, 256>>>();
    scanC_kernel<<<SCAN_B, 256>>>();
    fill_kernel<<<EB, 256>>>(edge);

    // ---- layer 1 ----
    gemm_kernel<IND><<<(NN + 63) / 64, 256>>>(x, W1, bufA, NN, as1, ad1);
    attn_kernel<0><<<WB, 256>>>(bufA, b1, bufB);

    // ---- layer 2 ----
    gemm_kernel<HID><<<(NN + 63) / 64, 256>>>(bufB, W2, bufA, NN, as2, ad2);
    attn_kernel<1><<<WB, 256>>>(bufA, b2, nullptr);

    head_kernel<<<NG, 32>>>(Wc, bc, out);
}